// round 16
// baseline (speedup 1.0000x reference)
#include <cuda_runtime.h>

#define MAXN 6016
#define NB   94                     // max number of 64-box blocks
#define TRI  (NB * (NB + 1) / 2)    // 4465 upper-triangle tiles
typedef unsigned long long u64;

// Scratch (device globals: allocation is banned; zero-initialized at load)
__device__ float4 g_sboxes[MAXN];
__device__ int    g_rank[MAXN];
__device__ u64    g_plist[MAXN];            // packed (score_bits<<32)|idx
__device__ __align__(16) u64 g_pool[(size_t)TRI * 64]; // nonzero tiles
__device__ u64    g_nzw[TRI];               // per-slot nonzero-row bitmap
__device__ u64    g_colOR[TRI];             // per-slot OR of all rows
__device__ int    g_meta[TRI];              // per-slot (rb<<16)|cb
__device__ int    g_poolcnt;                // slots used; reset by scan
__device__ int    g_cnt;                    // #prefix boxes; reset by scan

#define SCAN_THREADS 1024
// dynamic smem: nz[TRI] | kept/knew/und/remk/remu[NB] | meta[TRI] | wl[TRI] | cnt
#define SMEM_BYTES ((TRI + 5 * NB) * 8 + 2 * TRI * 4 + 16)

__device__ __forceinline__ int tri_start(int r) { return r * NB - (r * (r - 1)) / 2; }

__device__ __forceinline__ u64 redux_or64(u64 v) {
    unsigned lo = __reduce_or_sync(0xffffffffu, (unsigned)v);
    unsigned hi = __reduce_or_sync(0xffffffffu, (unsigned)(v >> 32));
    return (u64)lo | ((u64)hi << 32);
}

// ---------------------------------------------------------------------------
// 0) Compact prefix boxes (s >= 0.6) into g_plist.
// ---------------------------------------------------------------------------
__global__ void compact_kernel(const float* __restrict__ scores, int n) {
    int i = blockIdx.x * blockDim.x + threadIdx.x;
    if (i >= n) return;
    float s = scores[i];
    if (s >= 0.6f) {
        int p = atomicAdd(&g_cnt, 1);
        g_plist[p] = ((u64)__float_as_uint(s) << 32) | (unsigned)i;
    }
}

// ---------------------------------------------------------------------------
// 1) Rank within the prefix subset (== global rank for prefix boxes).
// ---------------------------------------------------------------------------
__global__ void rank_kernel(const float* __restrict__ boxes, int n) {
    const int w    = (blockIdx.x * blockDim.x + threadIdx.x) >> 5;
    const int lane = threadIdx.x & 31;
    const int m = g_cnt;
    if (w >= m) return;
    const u64 me = g_plist[w];
    const unsigned sb = (unsigned)(me >> 32);
    const unsigned ib = (unsigned)me;
    int cnt = 0;
    for (int j = lane; j < m; j += 32) {
        u64 e = g_plist[j];
        unsigned sj = (unsigned)(e >> 32);
        unsigned ij = (unsigned)e;
        cnt += (int)((sj > sb) | ((sj == sb) & (ij < ib)));
    }
    #pragma unroll
    for (int o = 16; o; o >>= 1) cnt += __shfl_down_sync(0xffffffffu, cnt, o);
    if (lane == 0) {
        g_sboxes[cnt] = ((const float4*)boxes)[ib];
        g_rank[ib]    = cnt;
    }
}

// ---------------------------------------------------------------------------
// 2) Suppression mask -> slot-indexed pool of NONZERO tiles, with per-slot
//    nonzero-row bitmap, full column-OR (for fixpoint round 1), and (rb,cb).
//    Slot order nondeterministic (atomicAdd) but all reads go through the
//    slot-indexed arrays, so output is deterministic.
// ---------------------------------------------------------------------------
__global__ void mask_kernel(int n) {
    int m = g_cnt; if (m > n) m = n;
    const int mb = (m + 63) >> 6;

    // linear tile -> (rb, cb) with cb >= rb
    const int p = blockIdx.x;
    int rb = (int)((2.0f * NB + 1.0f
                    - sqrtf((2.0f * NB + 1.0f) * (2.0f * NB + 1.0f) - 8.0f * p)) * 0.5f);
    if (rb < 0) rb = 0;
    while (rb + 1 <= NB - 1 && tri_start(rb + 1) <= p) rb++;
    while (rb > 0 && tri_start(rb) > p) rb--;
    const int cb = rb + (p - tri_start(rb));
    if (rb >= mb || cb >= mb) return;

    const int t = threadIdx.x;                   // 0..63
    __shared__ float4   cbox[64];                // {cz, cw, -cx, -cy}
    __shared__ float    carea[64];
    __shared__ unsigned nzhalf[2];
    __shared__ u64      corhalf[2];
    __shared__ int      slot_sh;
    const int col0 = cb * 64;
    if (col0 + t < m) {
        float4 c = g_sboxes[col0 + t];
        cbox[t]  = make_float4(c.z, c.w, -c.x, -c.y);
        carea[t] = (c.z - c.x) * (c.w - c.y);
    } else {
        cbox[t]  = make_float4(-1e30f, -1e30f, -1e30f, -1e30f);  // -> IoU 0
        carea[t] = 0.f;
    }
    __syncthreads();

    const int row = rb * 64 + t;
    const float4 b   = g_sboxes[row];            // stale if row>=m; bits forced 0
    const float  bz  = b.z,  bw  = b.w;
    const float  nbx = -b.x, nby = -b.y;
    const float  barea = (b.z - b.x) * (b.w - b.y);

    u64 bits = 0ULL;
    #pragma unroll
    for (int k = 0; k < 64; k++) {
        float4 c  = cbox[k];
        float iw  = fmaxf(fminf(bz, c.x) + fminf(nbx, c.z), 0.f);
        float ih  = fmaxf(fminf(bw, c.y) + fminf(nby, c.w), 0.f);
        float inter = iw * ih;
        float uni   = (barea + carea[k]) - inter;
        if (fmaf(-0.5f, uni, inter) > 0.f) bits |= (1ULL << k);
    }
    if (cb == rb) bits &= ((~1ULL) << t);        // keep only cols > row
    if (row >= m) bits = 0ULL;

    unsigned bal = __ballot_sync(0xffffffffu, bits != 0ULL);
    u64 cor = redux_or64(bits);
    if ((t & 31) == 0) { nzhalf[t >> 5] = bal; corhalf[t >> 5] = cor; }
    __syncthreads();
    if (t == 0) {
        u64 nzw = (u64)nzhalf[0] | ((u64)nzhalf[1] << 32);
        int s = -1;
        if (nzw != 0ULL) {
            s = atomicAdd(&g_poolcnt, 1);
            g_nzw[s]   = nzw;
            g_colOR[s] = corhalf[0] | corhalf[1];
            g_meta[s]  = (rb << 16) | cb;
        }
        slot_sh = s;
    }
    __syncthreads();
    const int s = slot_sh;
    if (s >= 0) g_pool[(size_t)s * 64 + t] = bits;
}

// ---------------------------------------------------------------------------
// 3) Incremental parallel-fixpoint greedy NMS + finalize, worklist form.
//    NO tile preload: each tile is consumed ~once (remk is persistent), so
//    Phase B reads g_pool directly with cached LDG — round 2's reads warm L1
//    (pool fits in 228KB L1), tail rounds hit L1. Round 1 needs no tile data
//    at all (precomputed column-ORs). Only nz/meta live in smem.
//    Decisions identical to the sequential greedy scan.
// ---------------------------------------------------------------------------
__global__ void scan_kernel(const float* __restrict__ scores,
                            float* __restrict__ out, int n) {
    extern __shared__ __align__(16) u64 dyn[];
    u64* nz_s   = dyn;                        // TRI
    u64* kept   = nz_s + TRI;                 // NB
    u64* knew   = kept + NB;                  // NB
    u64* und    = knew + NB;                  // NB
    u64* remk   = und + NB;                   // NB (persistent)
    u64* remu   = remk + NB;                  // NB (per-round)
    int* meta_s = (int*)(remu + NB);          // TRI
    int* wl     = meta_s + TRI;               // TRI
    int* wl_cnt = wl + TRI;                   // 1

    const int t = threadIdx.x;
    const int warp = t >> 5, lane = t & 31;
    int m = g_cnt; if (m > n) m = n;
    const int mb = (m + 63) >> 6;
    const int pct = g_poolcnt;

    for (int i = t; i < pct; i += SCAN_THREADS) {
        nz_s[i]   = g_nzw[i];
        meta_s[i] = g_meta[i];
    }
    if (t < NB) {
        kept[t] = 0ULL; knew[t] = 0ULL; remk[t] = 0ULL; remu[t] = 0ULL;
        const int vr = m - t * 64;
        und[t] = (vr >= 64) ? ~0ULL : ((vr > 0) ? ((1ULL << vr) - 1ULL) : 0ULL);
    }
    if (t == 0) *wl_cnt = 0;
    __syncthreads();

    // ---- Round 1: und = all valid -> remu via precomputed column-ORs ----
    for (int i = t; i < pct; i += SCAN_THREADS)
        atomicOr(&remu[meta_s[i] & 0xffff], g_colOR[i]);
    __syncthreads();
    int has_und = 0;
    if (t < NB) {
        const u64 u = und[t];
        u64 kn = 0ULL;
        if (u) {
            const u64 ru = remu[t];
            kn = u & ~ru;                      // remk is 0 in round 1
            kept[t] |= kn;
            und[t]   = u & ru;
        }
        knew[t] = kn;
        has_und = (und[t] != 0ULL);
        remu[t] = 0ULL;
    }
    const int live = __syncthreads_or(has_und);

    if (live) {
        for (;;) {
            // Phase A: parallel per-thread check -> worklist of active slots
            for (int i = t; i < pct; i += SCAN_THREADS) {
                const int rb = meta_s[i] >> 16;
                if (nz_s[i] & (knew[rb] | und[rb]))
                    wl[atomicAdd(wl_cnt, 1)] = i;
            }
            __syncthreads();

            // Phase B: full-warp processing of active tiles (L1-cached LDG)
            const int wc = *wl_cnt;
            for (int i = warp; i < wc; i += 32) {
                const int s  = wl[i];
                const int md = meta_s[s];
                const int rb = md >> 16, cb = md & 0xffff;
                const u64 kn = knew[rb], uw = und[rb];
                const u64* tl = g_pool + (size_t)s * 64;
                const u64 r0 = tl[lane], r1 = tl[lane + 32];
                u64 ak = (r0 & (0ULL - ((kn >> lane) & 1ULL)))
                       | (r1 & (0ULL - ((kn >> (lane + 32)) & 1ULL)));
                u64 au = (r0 & (0ULL - ((uw >> lane) & 1ULL)))
                       | (r1 & (0ULL - ((uw >> (lane + 32)) & 1ULL)));
                ak = redux_or64(ak);
                au = redux_or64(au);
                if (lane == 0) {
                    if (ak) atomicOr(&remk[cb], ak);
                    if (au) atomicOr(&remu[cb], au);
                }
            }
            __syncthreads();

            // Phase C: decide; remk persists, remu/worklist cleared
            int hu = 0;
            if (t < NB) {
                const u64 u = und[t];
                u64 kn = 0ULL;
                if (u) {
                    const u64 rk = remk[t], ru = remu[t];
                    kn = u & ~rk & ~ru;
                    kept[t] |= kn;
                    und[t]   = u & ru & ~rk;
                }
                knew[t] = kn;
                hu = (und[t] != 0ULL);
                remu[t] = 0ULL;
            }
            if (t == 0) *wl_cnt = 0;
            if (!__syncthreads_or(hu)) break;
        }
    }

    // Fused finalize: out[i] = s if (s >= 0.6 && kept) else 0
    for (int i = t; i < n; i += SCAN_THREADS) {
        float s = scores[i];
        float v = 0.0f;
        if (s >= 0.6f) {
            int r = g_rank[i];
            if ((kept[r >> 6] >> (r & 63)) & 1ULL) v = s;
        }
        out[i] = v;
    }

    if (t == 0) { g_cnt = 0; g_poolcnt = 0; }   // reset for next graph replay
}

// ---------------------------------------------------------------------------
extern "C" void kernel_launch(void* const* d_in, const int* in_sizes, int n_in,
                              void* d_out, int out_size) {
    const float* boxes  = (const float*)d_in[0];
    const float* scores = (const float*)d_in[1];
    const int n = in_sizes[1];                 // 6000

    cudaFuncSetAttribute(scan_kernel,
                         cudaFuncAttributeMaxDynamicSharedMemorySize, SMEM_BYTES);

    compact_kernel<<<(n + 255) / 256, 256>>>(scores, n);

    rank_kernel<<<(n * 32 + 255) / 256, 256>>>(boxes, n);

    mask_kernel<<<TRI, 64>>>(n);

    scan_kernel<<<1, SCAN_THREADS, SMEM_BYTES>>>(scores, (float*)d_out, n);
}

// round 17
// speedup vs baseline: 1.1631x; 1.1631x over previous
#include <cuda_runtime.h>

#define MAXN 6016
#define NB   94                     // max number of 64-box blocks
#define TRI  (NB * (NB + 1) / 2)    // 4465 upper-triangle tiles
#define MAXE (MAXN * NB)            // worst-case entry count (dense)
#define ESM  12288                  // entries resident in smem
typedef unsigned long long u64;

// Scratch (device globals: allocation is banned; zero-initialized at load)
__device__ float4 g_sboxes[MAXN];
__device__ int    g_rank[MAXN];
__device__ u64    g_plist[MAXN];    // packed (score_bits<<32)|idx
__device__ u64    g_ebits[MAXE];    // entry: 64-bit suppression word
__device__ int    g_emeta[MAXE];    // entry: (row<<7)|cb
__device__ int    g_ecnt;           // entries used; reset by scan
__device__ int    g_cnt;            // #prefix boxes; reset by scan

#define SCAN_THREADS 1024
// dynamic smem: ebits[ESM] | kept/knew/und/remk/remu[NB] | emeta[ESM]
#define SMEM_BYTES (ESM * 8 + 5 * NB * 8 + ESM * 4)

__device__ __forceinline__ int tri_start(int r) { return r * NB - (r * (r - 1)) / 2; }

// ---------------------------------------------------------------------------
// 0) Compact prefix boxes (s >= 0.6) into g_plist.
// ---------------------------------------------------------------------------
__global__ void compact_kernel(const float* __restrict__ scores, int n) {
    int i = blockIdx.x * blockDim.x + threadIdx.x;
    if (i >= n) return;
    float s = scores[i];
    if (s >= 0.6f) {
        int p = atomicAdd(&g_cnt, 1);
        g_plist[p] = ((u64)__float_as_uint(s) << 32) | (unsigned)i;
    }
}

// ---------------------------------------------------------------------------
// 1) Rank within the prefix subset (== global rank for prefix boxes).
// ---------------------------------------------------------------------------
__global__ void rank_kernel(const float* __restrict__ boxes, int n) {
    const int w    = (blockIdx.x * blockDim.x + threadIdx.x) >> 5;
    const int lane = threadIdx.x & 31;
    const int m = g_cnt;
    if (w >= m) return;
    const u64 me = g_plist[w];
    const unsigned sb = (unsigned)(me >> 32);
    const unsigned ib = (unsigned)me;
    int cnt = 0;
    for (int j = lane; j < m; j += 32) {
        u64 e = g_plist[j];
        unsigned sj = (unsigned)(e >> 32);
        unsigned ij = (unsigned)e;
        cnt += (int)((sj > sb) | ((sj == sb) & (ij < ib)));
    }
    #pragma unroll
    for (int o = 16; o; o >>= 1) cnt += __shfl_down_sync(0xffffffffu, cnt, o);
    if (lane == 0) {
        g_sboxes[cnt] = ((const float4*)boxes)[ib];
        g_rank[ib]    = cnt;
    }
}

// ---------------------------------------------------------------------------
// 2) Suppression mask -> flat ENTRY LIST of nonzero row-words:
//    g_emeta = (row<<7)|cb, g_ebits = 64-bit word (cols cb*64.. of row).
//    Entry order nondeterministic (atomicAdd) but downstream accumulation is
//    pure OR -> deterministic output.
// ---------------------------------------------------------------------------
__global__ void mask_kernel(int n) {
    int m = g_cnt; if (m > n) m = n;
    const int mb = (m + 63) >> 6;

    // linear tile -> (rb, cb) with cb >= rb
    const int p = blockIdx.x;
    int rb = (int)((2.0f * NB + 1.0f
                    - sqrtf((2.0f * NB + 1.0f) * (2.0f * NB + 1.0f) - 8.0f * p)) * 0.5f);
    if (rb < 0) rb = 0;
    while (rb + 1 <= NB - 1 && tri_start(rb + 1) <= p) rb++;
    while (rb > 0 && tri_start(rb) > p) rb--;
    const int cb = rb + (p - tri_start(rb));
    if (rb >= mb || cb >= mb) return;

    const int t = threadIdx.x;                   // 0..63
    __shared__ float4 cbox[64];                  // {cz, cw, -cx, -cy}
    __shared__ float  carea[64];
    const int col0 = cb * 64;
    if (col0 + t < m) {
        float4 c = g_sboxes[col0 + t];
        cbox[t]  = make_float4(c.z, c.w, -c.x, -c.y);
        carea[t] = (c.z - c.x) * (c.w - c.y);
    } else {
        cbox[t]  = make_float4(-1e30f, -1e30f, -1e30f, -1e30f);  // -> IoU 0
        carea[t] = 0.f;
    }
    __syncthreads();

    const int row = rb * 64 + t;
    if (row >= m) return;
    const float4 b   = g_sboxes[row];
    const float  bz  = b.z,  bw  = b.w;
    const float  nbx = -b.x, nby = -b.y;
    const float  barea = (b.z - b.x) * (b.w - b.y);

    u64 bits = 0ULL;
    #pragma unroll
    for (int k = 0; k < 64; k++) {
        float4 c  = cbox[k];
        float iw  = fmaxf(fminf(bz, c.x) + fminf(nbx, c.z), 0.f);
        float ih  = fmaxf(fminf(bw, c.y) + fminf(nby, c.w), 0.f);
        float inter = iw * ih;
        float uni   = (barea + carea[k]) - inter;
        if (fmaf(-0.5f, uni, inter) > 0.f) bits |= (1ULL << k);
    }
    if (cb == rb) bits &= ((~1ULL) << t);        // keep only cols > row

    if (bits) {
        int e = atomicAdd(&g_ecnt, 1);
        g_ebits[e] = bits;
        g_emeta[e] = (row << 7) | cb;
    }
}

// ---------------------------------------------------------------------------
// 3) Entry-list incremental parallel-fixpoint greedy NMS + finalize.
//    Per round, ONE ENTRY PER THREAD (~2-3 entries/thread total):
//      row newly kept  -> atomicOr(remk[cb], bits)   [applied exactly once]
//      row undecided   -> atomicOr(remu[cb], bits)   [rebuilt per round]
//    then decide per word: kept += und & ~remk & ~remu; und &= remu & ~remk.
//    knew and und are disjoint, so each live entry does at most one atomic;
//    dead entries cost ~6 instructions. Exact greedy-NMS result.
// ---------------------------------------------------------------------------
__global__ void scan_kernel(const float* __restrict__ scores,
                            float* __restrict__ out, int n) {
    extern __shared__ __align__(16) u64 dyn[];
    u64* eb_s  = dyn;                         // ESM
    u64* kept  = eb_s + ESM;                  // NB
    u64* knew  = kept + NB;                   // NB
    u64* und   = knew + NB;                   // NB
    u64* remk  = und + NB;                    // NB (persistent)
    u64* remu  = remk + NB;                   // NB (per-round)
    int* em_s  = (int*)(remu + NB);           // ESM

    const int t = threadIdx.x;
    int m = g_cnt; if (m > n) m = n;
    const int ec  = g_ecnt;
    const int ecs = (ec < ESM) ? ec : ESM;

    for (int i = t; i < ecs; i += SCAN_THREADS) {
        eb_s[i] = g_ebits[i];
        em_s[i] = g_emeta[i];
    }
    if (t < NB) {
        kept[t] = 0ULL; knew[t] = 0ULL; remk[t] = 0ULL; remu[t] = 0ULL;
        const int vr = m - t * 64;
        und[t] = (vr >= 64) ? ~0ULL : ((vr > 0) ? ((1ULL << vr) - 1ULL) : 0ULL);
    }
    __syncthreads();

    for (;;) {
        // Phase B: per-thread entry scan (round 1 falls out naturally:
        // knew=0, und=all -> every entry feeds remu)
        for (int i = t; i < ec; i += SCAN_THREADS) {
            const int md  = (i < ESM) ? em_s[i] : g_emeta[i];
            const int row = md >> 7;
            const int cb  = md & 127;
            const int rb  = row >> 6, bit = row & 63;
            const unsigned k = (unsigned)(knew[rb] >> bit) & 1u;
            const unsigned u = (unsigned)(und[rb]  >> bit) & 1u;
            if (k | u) {
                const u64 b = (i < ESM) ? eb_s[i] : g_ebits[i];
                if (k) atomicOr(&remk[cb], b);
                else   atomicOr(&remu[cb], b);
            }
        }
        __syncthreads();

        // Phase C: decide; remk persists, remu cleared
        int hu = 0;
        if (t < NB) {
            const u64 u = und[t];
            u64 kn = 0ULL;
            if (u) {
                const u64 rk = remk[t], ru = remu[t];
                kn = u & ~rk & ~ru;            // no kept & no undecided preds
                kept[t] |= kn;
                und[t]   = u & ru & ~rk;
            }
            knew[t] = kn;
            hu = (und[t] != 0ULL);
            remu[t] = 0ULL;
        }
        if (!__syncthreads_or(hu)) break;
    }

    // Fused finalize: out[i] = s if (s >= 0.6 && kept) else 0
    for (int i = t; i < n; i += SCAN_THREADS) {
        float s = scores[i];
        float v = 0.0f;
        if (s >= 0.6f) {
            int r = g_rank[i];
            if ((kept[r >> 6] >> (r & 63)) & 1ULL) v = s;
        }
        out[i] = v;
    }

    if (t == 0) { g_cnt = 0; g_ecnt = 0; }    // reset for next graph replay
}

// ---------------------------------------------------------------------------
extern "C" void kernel_launch(void* const* d_in, const int* in_sizes, int n_in,
                              void* d_out, int out_size) {
    const float* boxes  = (const float*)d_in[0];
    const float* scores = (const float*)d_in[1];
    const int n = in_sizes[1];                 // 6000

    cudaFuncSetAttribute(scan_kernel,
                         cudaFuncAttributeMaxDynamicSharedMemorySize, SMEM_BYTES);

    compact_kernel<<<(n + 255) / 256, 256>>>(scores, n);

    rank_kernel<<<(n * 32 + 255) / 256, 256>>>(boxes, n);

    mask_kernel<<<TRI, 64>>>(n);

    scan_kernel<<<1, SCAN_THREADS, SMEM_BYTES>>>(scores, (float*)d_out, n);
}